// round 15
// baseline (speedup 1.0000x reference)
#include <cuda_runtime.h>
#include <cuda_bf16.h>
#include <cstdint>
#include <math.h>

#define N_MAX   100000
#define E_MAX   1600000
#define G_NUM   64

typedef unsigned long long ull;

// ---------------- scratch (device globals; no allocation) ----------------
__device__ __align__(16) float g_xl[N_MAX * 64];
__device__ __align__(16) float g_xr[N_MAX * 64];
__device__ __align__(16) float g_xs[N_MAX * 64];
__device__ __align__(16) float g_out[N_MAX * 64];
__device__ int   g_deg[N_MAX];
__device__ int   g_off[N_MAX];
__device__ int   g_cur[N_MAX];
__device__ int   g_csr[E_MAX];
__device__ int   g_bsum[1024];
__device__ float g_sumM[G_NUM * 64];
__device__ float g_sqM [G_NUM * 64];
__device__ float g_sumS[G_NUM * 64];
__device__ float g_sqS [G_NUM * 64];
__device__ float g_cnt [G_NUM];
// bf16 hi/lo weight fragments in m16n8k16 B-layout: [ks(8)][nt(24)][lane(32)]{b0h,b1h,b0l,b1l}
__device__ __align__(16) uint4 g_wfrag[8 * 24 * 32];

// ---------------- helpers ----------------
__device__ __forceinline__ uint32_t f2bf2(float a, float b) {
    __nv_bfloat162 t = __floats2bfloat162_rn(a, b);   // .x = a = low half
    uint32_t r; memcpy(&r, &t, 4); return r;
}
__device__ __forceinline__ void bf2_split(float x0, float x1, uint32_t& hi, uint32_t& lo) {
    hi = f2bf2(x0, x1);
    float h0 = __uint_as_float(hi << 16);
    float h1 = __uint_as_float(hi & 0xFFFF0000u);
    lo = f2bf2(x0 - h0, x1 - h1);
}
__device__ __forceinline__ void mma16816(float* d, const uint32_t* a, uint32_t b0, uint32_t b1) {
    asm volatile(
        "mma.sync.aligned.m16n8k16.row.col.f32.bf16.bf16.f32 "
        "{%0,%1,%2,%3}, {%4,%5,%6,%7}, {%8,%9}, {%0,%1,%2,%3};"
        : "+f"(d[0]), "+f"(d[1]), "+f"(d[2]), "+f"(d[3])
        : "r"(a[0]), "r"(a[1]), "r"(a[2]), "r"(a[3]), "r"(b0), "r"(b1));
}

// ---------------- K0: init ----------------
__global__ void k_init(int N) {
    int i = blockIdx.x * blockDim.x + threadIdx.x;
    if (i < N) g_deg[i] = 0;
    if (i < G_NUM * 64) { g_sumM[i] = 0.f; g_sqM[i] = 0.f; g_sumS[i] = 0.f; g_sqS[i] = 0.f; }
    if (i < G_NUM) g_cnt[i] = 0.f;
}
__global__ void k_hist(const int* __restrict__ ei, int E) {
    int i = blockIdx.x * blockDim.x + threadIdx.x;
    if (i < E) atomicAdd(&g_deg[ei[E + i]], 1);
}

__global__ __launch_bounds__(1024) void k_scan1(int N) {
    __shared__ int s[1024];
    int tid = threadIdx.x;
    int i = blockIdx.x * 1024 + tid;
    int v = (i < N) ? g_deg[i] : 0;
    s[tid] = v;
    #pragma unroll
    for (int d = 1; d < 1024; d <<= 1) {
        __syncthreads();
        int t = (tid >= d) ? s[tid - d] : 0;
        __syncthreads();
        s[tid] += t;
    }
    __syncthreads();
    if (i < N) g_off[i] = s[tid] - v;
    if (tid == 1023) g_bsum[blockIdx.x] = s[1023];
}

__global__ __launch_bounds__(1024) void k_scan2(int nb) {
    __shared__ int s[1024];
    int tid = threadIdx.x;
    int v = (tid < nb) ? g_bsum[tid] : 0;
    s[tid] = v;
    #pragma unroll
    for (int d = 1; d < 1024; d <<= 1) {
        __syncthreads();
        int t = (tid >= d) ? s[tid - d] : 0;
        __syncthreads();
        s[tid] += t;
    }
    __syncthreads();
    if (tid < nb) g_bsum[tid] = s[tid] - v;
}

__global__ void k_scan3(int N) {
    int i = blockIdx.x * blockDim.x + threadIdx.x;
    if (i >= N) return;
    int o = g_off[i] + g_bsum[i >> 10];
    g_off[i] = o;
    g_cur[i] = o;
}

__global__ void k_fill(const int* __restrict__ ei, int E) {
    int i = blockIdx.x * blockDim.x + threadIdx.x;
    if (i >= E) return;
    int dst = ei[E + i];
    int pos = atomicAdd(&g_cur[dst], 1);
    g_csr[pos] = ei[i];
}

// ---------------- K_wprep: W -> bf16 hi/lo mma B-fragments ----------------
__global__ void k_wprep(const float* __restrict__ Wl, const float* __restrict__ Wr,
                        const float* __restrict__ Ws) {
    int idx = blockIdx.x * blockDim.x + threadIdx.x;
    if (idx >= 8 * 24 * 32) return;
    int lane = idx & 31;
    int nt = (idx >> 5) % 24;
    int ks = idx / (24 * 32);
    int g = lane >> 2, t = lane & 3;
    int n = nt * 8 + g;
    int k0 = ks * 16 + 2 * t;
    const float* W = (n < 64) ? Wl : ((n < 128) ? Wr : Ws);
    int wn = n & 63;
    float x0 = __ldg(W + (k0)     * 64 + wn);
    float x1 = __ldg(W + (k0 + 1) * 64 + wn);
    float x2 = __ldg(W + (k0 + 8) * 64 + wn);
    float x3 = __ldg(W + (k0 + 9) * 64 + wn);
    uint4 o;
    uint32_t h, l;
    bf2_split(x0, x1, h, l); o.x = h; o.z = l;
    bf2_split(x2, x3, h, l); o.y = h; o.w = l;
    g_wfrag[idx] = o;
}

// ---------------- K1: mma.sync bf16x3 GEMM, 128 rows x 192 cols per block ----------------
#define WSMEM (8 * 24 * 32 * 16)   // 98304
__global__ __launch_bounds__(512) void k_gemmT(
    const float* __restrict__ x, const float* __restrict__ skip_b, int N)
{
    extern __shared__ uint4 sB[];   // [ks][nt][lane] 16B each
    int tid = threadIdx.x;
    int warp = tid >> 5, lane = tid & 31;
    int strip = warp & 7, colhalf = warp >> 3;
    int g = lane >> 2, t = lane & 3;

    // stage B fragments
    for (int i = tid; i < 8 * 24 * 32; i += 512) {
        unsigned int da;
        asm("{ .reg .u64 u; cvta.to.shared.u64 u, %1; cvt.u32.u64 %0, u; }"
            : "=r"(da) : "l"(sB + i));
        const uint4* src = g_wfrag + i;
        asm volatile("cp.async.cg.shared.global [%0], [%1], 16;" :: "r"(da), "l"(src));
    }
    asm volatile("cp.async.commit_group;");

    int R = blockIdx.x * 128 + strip * 16;
    int rA = R + g, rB = R + 8 + g;
    bool vA = rA < N, vB = rB < N;
    const float* xA = x + (size_t)rA * 128;
    const float* xB = x + (size_t)rB * 128;

    float D[12][4];
    #pragma unroll
    for (int i = 0; i < 12; i++)
        #pragma unroll
        for (int j = 0; j < 4; j++) D[i][j] = 0.f;

    asm volatile("cp.async.wait_group 0;");
    __syncthreads();

    #pragma unroll 1
    for (int ks = 0; ks < 8; ks++) {
        int kb = ks * 16 + 2 * t;
        float2 z = make_float2(0.f, 0.f);
        float2 p0 = vA ? *(const float2*)(xA + kb)     : z;
        float2 p2 = vA ? *(const float2*)(xA + kb + 8) : z;
        float2 p1 = vB ? *(const float2*)(xB + kb)     : z;
        float2 p3 = vB ? *(const float2*)(xB + kb + 8) : z;

        uint32_t ah[4], al[4];
        bf2_split(p0.x, p0.y, ah[0], al[0]);
        bf2_split(p1.x, p1.y, ah[1], al[1]);
        bf2_split(p2.x, p2.y, ah[2], al[2]);
        bf2_split(p3.x, p3.y, ah[3], al[3]);

        const uint4* bp = sB + (ks * 24 + colhalf * 12) * 32 + lane;
        #pragma unroll
        for (int nt = 0; nt < 12; nt++) {
            uint4 B4 = bp[nt * 32];
            mma16816(D[nt], ah, B4.x, B4.y);   // Ah * Bh
            mma16816(D[nt], ah, B4.z, B4.w);   // Ah * Bl
            mma16816(D[nt], al, B4.x, B4.y);   // Al * Bh
        }
    }

    // epilogue
    #pragma unroll
    for (int nt = 0; nt < 12; nt++) {
        int cbase = (colhalf * 12 + nt) * 8;
        float* dst = (cbase < 64) ? g_xl : ((cbase < 128) ? g_xr : g_xs);
        int c = (cbase & 63) + 2 * t;
        float add0 = 0.f, add1 = 0.f;
        if (cbase >= 128) { add0 = __ldg(skip_b + c); add1 = __ldg(skip_b + c + 1); }
        if (vA) {
            float2 v; v.x = D[nt][0] + add0; v.y = D[nt][1] + add1;
            *(float2*)(dst + (size_t)rA * 64 + c) = v;
        }
        if (vB) {
            float2 v; v.x = D[nt][2] + add0; v.y = D[nt][3] + add1;
            *(float2*)(dst + (size_t)rB * 64 + c) = v;
        }
    }
}

// ---------------- K2: per-dst softmax-aggregate, no-max, 2 edges/warp, float4 ----------------
__global__ __launch_bounds__(256) void k_edge(
    const float* __restrict__ att, const float* __restrict__ conv_bias, int N, int E)
{
    int gw = (blockIdx.x * blockDim.x + threadIdx.x) >> 5;
    if (gw >= N) return;
    int lane = threadIdx.x & 31;
    int half = lane >> 4;
    int l = lane & 15;
    int d = gw;
    unsigned hmask = half ? 0xFFFF0000u : 0x0000FFFFu;

    const float4* xl4 = (const float4*)g_xl;
    float4 xr = __ldg((const float4*)g_xr + (size_t)d * 16 + l);
    float4 at = __ldg((const float4*)att + l);

    float den = 0.f, s0 = 0.f, s1 = 0.f, s2 = 0.f, s3 = 0.f;

    int e0  = g_off[d];
    int end = (d + 1 < N) ? g_off[d + 1] : E;
    int nE  = end - e0;
    int cnt = (nE - half + 1) >> 1;
    if (cnt < 0) cnt = 0;
    int base = e0 + half;

    if (half == 1) {
        float4 v = __ldg(xl4 + (size_t)d * 16 + l);
        float t0 = v.x + xr.x, t1 = v.y + xr.y, t2 = v.z + xr.z, t3 = v.w + xr.w;
        t0 = t0 > 0.f ? t0 : 0.2f * t0;
        t1 = t1 > 0.f ? t1 : 0.2f * t1;
        t2 = t2 > 0.f ? t2 : 0.2f * t2;
        t3 = t3 > 0.f ? t3 : 0.2f * t3;
        float p = fmaf(t0, at.x, fmaf(t1, at.y, fmaf(t2, at.z, t3 * at.w)));
        p += __shfl_xor_sync(hmask, p, 1);
        p += __shfl_xor_sync(hmask, p, 2);
        float ex = __expf(p);
        den += ex;
        s0 = fmaf(v.x, ex, s0);
        s1 = fmaf(v.y, ex, s1);
        s2 = fmaf(v.z, ex, s2);
        s3 = fmaf(v.w, ex, s3);
    } else {
        float p = 0.f;
        p += __shfl_xor_sync(hmask, p, 1);
        p += __shfl_xor_sync(hmask, p, 2);
    }

    #pragma unroll 8
    for (int it = 0; it < cnt; it++) {
        int src = __ldg(&g_csr[base + 2 * it]);
        float4 v = __ldg(xl4 + (size_t)src * 16 + l);
        float t0 = v.x + xr.x, t1 = v.y + xr.y, t2 = v.z + xr.z, t3 = v.w + xr.w;
        t0 = t0 > 0.f ? t0 : 0.2f * t0;
        t1 = t1 > 0.f ? t1 : 0.2f * t1;
        t2 = t2 > 0.f ? t2 : 0.2f * t2;
        t3 = t3 > 0.f ? t3 : 0.2f * t3;
        float p = fmaf(t0, at.x, fmaf(t1, at.y, fmaf(t2, at.z, t3 * at.w)));
        p += __shfl_xor_sync(hmask, p, 1);
        p += __shfl_xor_sync(hmask, p, 2);
        float ex = __expf(p);
        den += ex;
        s0 = fmaf(v.x, ex, s0);
        s1 = fmaf(v.y, ex, s1);
        s2 = fmaf(v.z, ex, s2);
        s3 = fmaf(v.w, ex, s3);
    }

    __syncwarp();
    den += __shfl_xor_sync(0xffffffffu, den, 16);
    s0  += __shfl_xor_sync(0xffffffffu, s0, 16);
    s1  += __shfl_xor_sync(0xffffffffu, s1, 16);
    s2  += __shfl_xor_sync(0xffffffffu, s2, 16);
    s3  += __shfl_xor_sync(0xffffffffu, s3, 16);

    if (half == 0) {
        float inv = 1.f / den;
        float4 cb = __ldg((const float4*)conv_bias + l);
        float4 o;
        o.x = fmaf(s0, inv, cb.x);
        o.y = fmaf(s1, inv, cb.y);
        o.z = fmaf(s2, inv, cb.z);
        o.w = fmaf(s3, inv, cb.w);
        ((float4*)g_out)[(size_t)d * 16 + l] = o;
    }
}

// ---------------- K3a: skip-branch sums (only needs gemm) ----------------
__global__ __launch_bounds__(256) void k_statsS(const int* __restrict__ batch, int N)
{
    int gid = blockIdx.x * blockDim.x + threadIdx.x;
    int ch = gid & 63;
    int slot = gid >> 6;
    int n0 = slot * 32;
    if (n0 >= N) return;
    int n1 = min(n0 + 32, N);

    int gfirst = batch[n0], glast = batch[n1 - 1];
    if (gfirst == glast) {
        float aS = 0.f, qS = 0.f;
        #pragma unroll 4
        for (int n = n0; n < n1; n++) {
            float vs = g_xs[(size_t)n * 64 + ch];
            aS += vs; qS = fmaf(vs, vs, qS);
        }
        atomicAdd(&g_sumS[gfirst * 64 + ch], aS);
        atomicAdd(&g_sqS [gfirst * 64 + ch], qS);
        if (ch == 0) atomicAdd(&g_cnt[gfirst], (float)(n1 - n0));
        return;
    }

    float aS = 0.f, qS = 0.f, ac = 0.f;
    int curg = gfirst;
    for (int n = n0; n < n1; n++) {
        int g = batch[n];
        if (g != curg) {
            atomicAdd(&g_sumS[curg * 64 + ch], aS);
            atomicAdd(&g_sqS [curg * 64 + ch], qS);
            if (ch == 0) atomicAdd(&g_cnt[curg], ac);
            aS = qS = ac = 0.f; curg = g;
        }
        float vs = g_xs[(size_t)n * 64 + ch];
        aS += vs; qS = fmaf(vs, vs, qS);
        ac += 1.f;
    }
    atomicAdd(&g_sumS[curg * 64 + ch], aS);
    atomicAdd(&g_sqS [curg * 64 + ch], qS);
    if (ch == 0) atomicAdd(&g_cnt[curg], ac);
}

// ---------------- K3b: main-branch sums (needs edge output) ----------------
__global__ __launch_bounds__(256) void k_statsM(const int* __restrict__ batch, int N)
{
    int gid = blockIdx.x * blockDim.x + threadIdx.x;
    int ch = gid & 63;
    int slot = gid >> 6;
    int n0 = slot * 32;
    if (n0 >= N) return;
    int n1 = min(n0 + 32, N);

    int gfirst = batch[n0], glast = batch[n1 - 1];
    if (gfirst == glast) {
        float aM = 0.f, qM = 0.f;
        #pragma unroll 4
        for (int n = n0; n < n1; n++) {
            float vm = g_out[(size_t)n * 64 + ch];
            aM += vm; qM = fmaf(vm, vm, qM);
        }
        atomicAdd(&g_sumM[gfirst * 64 + ch], aM);
        atomicAdd(&g_sqM [gfirst * 64 + ch], qM);
        return;
    }

    float aM = 0.f, qM = 0.f;
    int curg = gfirst;
    for (int n = n0; n < n1; n++) {
        int g = batch[n];
        if (g != curg) {
            atomicAdd(&g_sumM[curg * 64 + ch], aM);
            atomicAdd(&g_sqM [curg * 64 + ch], qM);
            aM = qM = 0.f; curg = g;
        }
        float vm = g_out[(size_t)n * 64 + ch];
        aM += vm; qM = fmaf(vm, vm, qM);
    }
    atomicAdd(&g_sumM[curg * 64 + ch], aM);
    atomicAdd(&g_sqM [curg * 64 + ch], qM);
}

// ---------------- K3c: precompute per-(graph,channel) affine coeffs ----------------
__global__ void k_prec(
    const float* __restrict__ bn_w, const float* __restrict__ bn_b, const float* __restrict__ bn_ms,
    const float* __restrict__ sn_w, const float* __restrict__ sn_b, const float* __restrict__ sn_ms)
{
    int i = blockIdx.x * blockDim.x + threadIdx.x;
    if (i >= G_NUM * 64) return;
    int g = i >> 6, ch = i & 63;
    float cntv = fmaxf(g_cnt[g], 1.f);
    float rinv = 1.f / cntv;
    float msM = bn_ms[ch], msS = sn_ms[ch];

    float meanM = g_sumM[i] * rinv;
    float eqM   = g_sqM [i] * rinv;
    float varM  = fmaxf(eqM - meanM * meanM * msM * (2.f - msM), 0.f);
    float meanS = g_sumS[i] * rinv;
    float eqS   = g_sqS [i] * rinv;
    float varS  = fmaxf(eqS - meanS * meanS * msS * (2.f - msS), 0.f);

    float cM = bn_w[ch] * rsqrtf(varM + 1e-5f);
    float cS = sn_w[ch] * rsqrtf(varS + 1e-5f);
    float C  = bn_b[ch] + sn_b[ch] - cM * meanM * msM - cS * meanS * msS;
    g_sumM[i] = cM;
    g_sumS[i] = cS;
    g_sqM [i] = C;
}

// ---------------- K4: y = cM*vm + cS*vs + C, then ELU (float4) ----------------
__global__ __launch_bounds__(256) void k_final(
    const int* __restrict__ batch, float* __restrict__ out, int N)
{
    int i = blockIdx.x * blockDim.x + threadIdx.x;
    if (i >= N * 16) return;
    int n = i >> 4, q = i & 15;
    int g = batch[n];

    float4 cM = ((const float4*)g_sumM)[g * 16 + q];
    float4 cS = ((const float4*)g_sumS)[g * 16 + q];
    float4 C  = ((const float4*)g_sqM )[g * 16 + q];
    float4 vm = ((const float4*)g_out)[i];
    float4 vs = ((const float4*)g_xs)[i];

    float4 res;
    float y;
    y = fmaf(cM.x, vm.x, fmaf(cS.x, vs.x, C.x)); res.x = (y > 0.f) ? y : (__expf(y) - 1.f);
    y = fmaf(cM.y, vm.y, fmaf(cS.y, vs.y, C.y)); res.y = (y > 0.f) ? y : (__expf(y) - 1.f);
    y = fmaf(cM.z, vm.z, fmaf(cS.z, vs.z, C.z)); res.z = (y > 0.f) ? y : (__expf(y) - 1.f);
    y = fmaf(cM.w, vm.w, fmaf(cS.w, vs.w, C.w)); res.w = (y > 0.f) ? y : (__expf(y) - 1.f);
    ((float4*)out)[i] = res;
}

// ---------------- launch (fork-join; gemmT submitted 4th for ncu) ----------------
extern "C" void kernel_launch(void* const* d_in, const int* in_sizes, int n_in,
                              void* d_out, int out_size)
{
    const float* x         = (const float*)d_in[0];
    const int*   ei        = (const int*)d_in[1];
    const int*   batch     = (const int*)d_in[2];
    const float* Wl        = (const float*)d_in[3];
    const float* Wr        = (const float*)d_in[4];
    const float* att       = (const float*)d_in[5];
    const float* conv_bias = (const float*)d_in[6];
    const float* skip_W    = (const float*)d_in[7];
    const float* skip_b    = (const float*)d_in[8];
    const float* bn_w      = (const float*)d_in[9];
    const float* bn_b      = (const float*)d_in[10];
    const float* bn_ms     = (const float*)d_in[11];
    const float* sn_w      = (const float*)d_in[12];
    const float* sn_b      = (const float*)d_in[13];
    const float* sn_ms     = (const float*)d_in[14];
    float*       out       = (float*)d_out;

    int N  = in_sizes[0] / 128;
    int E  = in_sizes[1] / 2;
    int nb = (N + 1023) / 1024;

    static cudaStream_t s1 = nullptr;
    static cudaEvent_t evFork = nullptr, evJoin = nullptr, evGemm = nullptr, evS = nullptr;
    if (s1 == nullptr) {
        cudaStreamCreateWithFlags(&s1, cudaStreamNonBlocking);
        cudaEventCreateWithFlags(&evFork, cudaEventDisableTiming);
        cudaEventCreateWithFlags(&evJoin, cudaEventDisableTiming);
        cudaEventCreateWithFlags(&evGemm, cudaEventDisableTiming);
        cudaEventCreateWithFlags(&evS, cudaEventDisableTiming);
        cudaFuncSetAttribute(k_gemmT, cudaFuncAttributeMaxDynamicSharedMemorySize, WSMEM);
    }

    // fork
    cudaEventRecord(evFork, 0);
    cudaStreamWaitEvent(s1, evFork, 0);

    // launch #1: wprep (main)
    k_wprep<<<(8 * 24 * 32 + 255) / 256, 256>>>(Wl, Wr, skip_W);
    // launches #2-#3: start of CSR chain (s1)
    k_init <<<(N + 255) / 256, 256, 0, s1>>>(N);
    k_hist <<<(E + 255) / 256, 256, 0, s1>>>(ei, E);
    // launch #4: gemmT (main)  <- ncu-profiled slot
    k_gemmT<<<(N + 127) / 128, 512, WSMEM>>>(x, skip_b, N);
    cudaEventRecord(evGemm, 0);
    // rest of CSR chain (s1)
    k_scan1<<<nb, 1024, 0, s1>>>(N);
    k_scan2<<<1, 1024, 0, s1>>>(nb);
    k_scan3<<<(N + 255) / 256, 256, 0, s1>>>(N);
    k_fill <<<(E + 255) / 256, 256, 0, s1>>>(ei, E);
    cudaEventRecord(evJoin, s1);

    // statsS overlaps edge on side stream
    cudaStreamWaitEvent(s1, evGemm, 0);
    {
        int slots = (N + 31) / 32;
        long long threads = (long long)slots * 64;
        k_statsS<<<(unsigned)((threads + 255) / 256), 256, 0, s1>>>(batch, N);
    }
    cudaEventRecord(evS, s1);

    // join: edge needs both GEMM output and CSR
    cudaStreamWaitEvent(0, evJoin, 0);

    {   // edge: 1 warp per node
        long long threads = (long long)N * 32;
        k_edge<<<(unsigned)((threads + 255) / 256), 256>>>(att, conv_bias, N, E);
    }
    {   // statsM
        int slots = (N + 31) / 32;
        long long threads = (long long)slots * 64;
        k_statsM<<<(unsigned)((threads + 255) / 256), 256>>>(batch, N);
    }
    cudaStreamWaitEvent(0, evS, 0);
    k_prec<<<(G_NUM * 64 + 255) / 256, 256>>>(bn_w, bn_b, bn_ms, sn_w, sn_b, sn_ms);
    {   // final
        long long total = (long long)N * 16;
        k_final<<<(unsigned)((total + 255) / 256), 256>>>(batch, out, N);
    }
}

// round 16
// speedup vs baseline: 1.0261x; 1.0261x over previous
#include <cuda_runtime.h>
#include <cuda_bf16.h>
#include <cstdint>
#include <math.h>

#define N_MAX   100000
#define E_MAX   1600000
#define G_NUM   64

typedef unsigned long long ull;

// ---------------- scratch (device globals; no allocation) ----------------
__device__ __align__(16) float g_xl[N_MAX * 64];
__device__ __align__(16) float g_xr[N_MAX * 64];
__device__ __align__(16) float g_xs[N_MAX * 64];
__device__ __align__(16) float g_out[N_MAX * 64];
__device__ int   g_deg[N_MAX];
__device__ int   g_off[N_MAX];
__device__ int   g_cur[N_MAX];
__device__ int   g_csr[E_MAX];
__device__ int   g_bsum[1024];
__device__ float g_sumM[G_NUM * 64];
__device__ float g_sqM [G_NUM * 64];
__device__ float g_sumS[G_NUM * 64];
__device__ float g_sqS [G_NUM * 64];
__device__ float g_cnt [G_NUM];
// bf16 hi/lo weight fragments in m16n8k16 B-layout: [ks(8)][nt(24)][lane(32)]{b0h,b1h,b0l,b1l}
__device__ __align__(16) uint4 g_wfrag[8 * 24 * 32];

// ---------------- helpers ----------------
__device__ __forceinline__ uint32_t f2bf2(float a, float b) {
    __nv_bfloat162 t = __floats2bfloat162_rn(a, b);   // .x = a = low half
    uint32_t r; memcpy(&r, &t, 4); return r;
}
__device__ __forceinline__ void bf2_split(float x0, float x1, uint32_t& hi, uint32_t& lo) {
    hi = f2bf2(x0, x1);
    float h0 = __uint_as_float(hi << 16);
    float h1 = __uint_as_float(hi & 0xFFFF0000u);
    lo = f2bf2(x0 - h0, x1 - h1);
}
__device__ __forceinline__ void mma16816(float* d, const uint32_t* a, uint32_t b0, uint32_t b1) {
    asm volatile(
        "mma.sync.aligned.m16n8k16.row.col.f32.bf16.bf16.f32 "
        "{%0,%1,%2,%3}, {%4,%5,%6,%7}, {%8,%9}, {%0,%1,%2,%3};"
        : "+f"(d[0]), "+f"(d[1]), "+f"(d[2]), "+f"(d[3])
        : "r"(a[0]), "r"(a[1]), "r"(a[2]), "r"(a[3]), "r"(b0), "r"(b1));
}

// ---------------- K0: init ----------------
__global__ void k_init(int N) {
    int i = blockIdx.x * blockDim.x + threadIdx.x;
    if (i < N) g_deg[i] = 0;
    if (i < G_NUM * 64) { g_sumM[i] = 0.f; g_sqM[i] = 0.f; g_sumS[i] = 0.f; g_sqS[i] = 0.f; }
    if (i < G_NUM) g_cnt[i] = 0.f;
}
__global__ void k_hist(const int* __restrict__ ei, int E) {
    int i = blockIdx.x * blockDim.x + threadIdx.x;
    if (i < E) atomicAdd(&g_deg[ei[E + i]], 1);
}

__global__ __launch_bounds__(1024) void k_scan1(int N) {
    __shared__ int s[1024];
    int tid = threadIdx.x;
    int i = blockIdx.x * 1024 + tid;
    int v = (i < N) ? g_deg[i] : 0;
    s[tid] = v;
    #pragma unroll
    for (int d = 1; d < 1024; d <<= 1) {
        __syncthreads();
        int t = (tid >= d) ? s[tid - d] : 0;
        __syncthreads();
        s[tid] += t;
    }
    __syncthreads();
    if (i < N) g_off[i] = s[tid] - v;
    if (tid == 1023) g_bsum[blockIdx.x] = s[1023];
}

__global__ __launch_bounds__(1024) void k_scan2(int nb) {
    __shared__ int s[1024];
    int tid = threadIdx.x;
    int v = (tid < nb) ? g_bsum[tid] : 0;
    s[tid] = v;
    #pragma unroll
    for (int d = 1; d < 1024; d <<= 1) {
        __syncthreads();
        int t = (tid >= d) ? s[tid - d] : 0;
        __syncthreads();
        s[tid] += t;
    }
    __syncthreads();
    if (tid < nb) g_bsum[tid] = s[tid] - v;
}

__global__ void k_scan3(int N) {
    int i = blockIdx.x * blockDim.x + threadIdx.x;
    if (i >= N) return;
    int o = g_off[i] + g_bsum[i >> 10];
    g_off[i] = o;
    g_cur[i] = o;
}

__global__ void k_fill(const int* __restrict__ ei, int E) {
    int i = blockIdx.x * blockDim.x + threadIdx.x;
    if (i >= E) return;
    int dst = ei[E + i];
    int pos = atomicAdd(&g_cur[dst], 1);
    g_csr[pos] = ei[i];
}

// ---------------- K_wprep: W -> bf16 hi/lo mma B-fragments ----------------
__global__ void k_wprep(const float* __restrict__ Wl, const float* __restrict__ Wr,
                        const float* __restrict__ Ws) {
    int idx = blockIdx.x * blockDim.x + threadIdx.x;
    if (idx >= 8 * 24 * 32) return;
    int lane = idx & 31;
    int nt = (idx >> 5) % 24;
    int ks = idx / (24 * 32);
    int g = lane >> 2, t = lane & 3;
    int n = nt * 8 + g;
    int k0 = ks * 16 + 2 * t;
    const float* W = (n < 64) ? Wl : ((n < 128) ? Wr : Ws);
    int wn = n & 63;
    float x0 = __ldg(W + (k0)     * 64 + wn);
    float x1 = __ldg(W + (k0 + 1) * 64 + wn);
    float x2 = __ldg(W + (k0 + 8) * 64 + wn);
    float x3 = __ldg(W + (k0 + 9) * 64 + wn);
    uint4 o;
    uint32_t h, l;
    bf2_split(x0, x1, h, l); o.x = h; o.z = l;
    bf2_split(x2, x3, h, l); o.y = h; o.w = l;
    g_wfrag[idx] = o;
}

// ---------------- K1a: GEMM for xl|xr (cols 0..127), 128 rows/block ----------------
#define SM_LR (8 * 16 * 32 * 16)   // 65536
__global__ __launch_bounds__(512) void k_gemm_lr(const float* __restrict__ x, int N)
{
    extern __shared__ uint4 sB[];   // [ks(8)][nt(16)][lane(32)]
    int tid = threadIdx.x;
    int warp = tid >> 5, lane = tid & 31;
    int strip = warp & 7, colhalf = warp >> 3;
    int g = lane >> 2, t = lane & 3;

    for (int i = tid; i < 8 * 16 * 32; i += 512) {
        int lane_i = i & 31;
        int nt = (i >> 5) & 15;
        int ks = i >> 9;
        unsigned int da;
        asm("{ .reg .u64 u; cvta.to.shared.u64 u, %1; cvt.u32.u64 %0, u; }"
            : "=r"(da) : "l"(sB + i));
        const uint4* src = g_wfrag + (ks * 24 + nt) * 32 + lane_i;
        asm volatile("cp.async.cg.shared.global [%0], [%1], 16;" :: "r"(da), "l"(src));
    }
    asm volatile("cp.async.commit_group;");

    int R = blockIdx.x * 128 + strip * 16;
    int rA = R + g, rB = R + 8 + g;
    bool vA = rA < N, vB = rB < N;
    const float* xA = x + (size_t)rA * 128;
    const float* xB = x + (size_t)rB * 128;

    float D[8][4];
    #pragma unroll
    for (int i = 0; i < 8; i++)
        #pragma unroll
        for (int j = 0; j < 4; j++) D[i][j] = 0.f;

    asm volatile("cp.async.wait_group 0;");
    __syncthreads();

    float2 z = make_float2(0.f, 0.f);
    int kb0 = 2 * t;
    float2 pA0 = vA ? *(const float2*)(xA + kb0)     : z;
    float2 pB0 = vB ? *(const float2*)(xB + kb0)     : z;
    float2 pA1 = vA ? *(const float2*)(xA + kb0 + 8) : z;
    float2 pB1 = vB ? *(const float2*)(xB + kb0 + 8) : z;

    #pragma unroll 1
    for (int ks = 0; ks < 8; ks++) {
        float2 qA0, qB0, qA1, qB1;
        if (ks < 7) {
            int kb = (ks + 1) * 16 + 2 * t;
            qA0 = vA ? *(const float2*)(xA + kb)     : z;
            qB0 = vB ? *(const float2*)(xB + kb)     : z;
            qA1 = vA ? *(const float2*)(xA + kb + 8) : z;
            qB1 = vB ? *(const float2*)(xB + kb + 8) : z;
        }
        uint32_t ah[4], al[4];
        bf2_split(pA0.x, pA0.y, ah[0], al[0]);
        bf2_split(pB0.x, pB0.y, ah[1], al[1]);
        bf2_split(pA1.x, pA1.y, ah[2], al[2]);
        bf2_split(pB1.x, pB1.y, ah[3], al[3]);

        const uint4* bp = sB + (ks * 16 + colhalf * 8) * 32 + lane;
        #pragma unroll
        for (int nt = 0; nt < 8; nt++) {
            uint4 B4 = bp[nt * 32];
            mma16816(D[nt], ah, B4.x, B4.y);
            mma16816(D[nt], ah, B4.z, B4.w);
            mma16816(D[nt], al, B4.x, B4.y);
        }
        pA0 = qA0; pB0 = qB0; pA1 = qA1; pB1 = qB1;
    }

    #pragma unroll
    for (int nt = 0; nt < 8; nt++) {
        int cbase = (colhalf * 8 + nt) * 8;          // 0..127
        float* dst = (cbase < 64) ? g_xl : g_xr;
        int c = (cbase & 63) + 2 * t;
        if (vA) { float2 v; v.x = D[nt][0]; v.y = D[nt][1]; *(float2*)(dst + (size_t)rA * 64 + c) = v; }
        if (vB) { float2 v; v.x = D[nt][2]; v.y = D[nt][3]; *(float2*)(dst + (size_t)rB * 64 + c) = v; }
    }
}

// ---------------- K1b: GEMM for xs (cols 128..191), 128 rows/block ----------------
#define SM_S (8 * 8 * 32 * 16)   // 32768
__global__ __launch_bounds__(256) void k_gemm_s(
    const float* __restrict__ x, const float* __restrict__ skip_b, int N)
{
    extern __shared__ uint4 sB[];   // [ks(8)][nt(8)][lane(32)]
    int tid = threadIdx.x;
    int warp = tid >> 5, lane = tid & 31;
    int strip = warp;                 // 8 strips
    int g = lane >> 2, t = lane & 3;

    for (int i = tid; i < 8 * 8 * 32; i += 256) {
        int lane_i = i & 31;
        int nt = (i >> 5) & 7;
        int ks = i >> 8;
        unsigned int da;
        asm("{ .reg .u64 u; cvta.to.shared.u64 u, %1; cvt.u32.u64 %0, u; }"
            : "=r"(da) : "l"(sB + i));
        const uint4* src = g_wfrag + (ks * 24 + 16 + nt) * 32 + lane_i;
        asm volatile("cp.async.cg.shared.global [%0], [%1], 16;" :: "r"(da), "l"(src));
    }
    asm volatile("cp.async.commit_group;");

    int R = blockIdx.x * 128 + strip * 16;
    int rA = R + g, rB = R + 8 + g;
    bool vA = rA < N, vB = rB < N;
    const float* xA = x + (size_t)rA * 128;
    const float* xB = x + (size_t)rB * 128;

    float D[8][4];
    #pragma unroll
    for (int i = 0; i < 8; i++)
        #pragma unroll
        for (int j = 0; j < 4; j++) D[i][j] = 0.f;

    asm volatile("cp.async.wait_group 0;");
    __syncthreads();

    float2 z = make_float2(0.f, 0.f);
    int kb0 = 2 * t;
    float2 pA0 = vA ? *(const float2*)(xA + kb0)     : z;
    float2 pB0 = vB ? *(const float2*)(xB + kb0)     : z;
    float2 pA1 = vA ? *(const float2*)(xA + kb0 + 8) : z;
    float2 pB1 = vB ? *(const float2*)(xB + kb0 + 8) : z;

    #pragma unroll 1
    for (int ks = 0; ks < 8; ks++) {
        float2 qA0, qB0, qA1, qB1;
        if (ks < 7) {
            int kb = (ks + 1) * 16 + 2 * t;
            qA0 = vA ? *(const float2*)(xA + kb)     : z;
            qB0 = vB ? *(const float2*)(xB + kb)     : z;
            qA1 = vA ? *(const float2*)(xA + kb + 8) : z;
            qB1 = vB ? *(const float2*)(xB + kb + 8) : z;
        }
        uint32_t ah[4], al[4];
        bf2_split(pA0.x, pA0.y, ah[0], al[0]);
        bf2_split(pB0.x, pB0.y, ah[1], al[1]);
        bf2_split(pA1.x, pA1.y, ah[2], al[2]);
        bf2_split(pB1.x, pB1.y, ah[3], al[3]);

        const uint4* bp = sB + ks * 8 * 32 + lane;
        #pragma unroll
        for (int nt = 0; nt < 8; nt++) {
            uint4 B4 = bp[nt * 32];
            mma16816(D[nt], ah, B4.x, B4.y);
            mma16816(D[nt], ah, B4.z, B4.w);
            mma16816(D[nt], al, B4.x, B4.y);
        }
        pA0 = qA0; pB0 = qB0; pA1 = qA1; pB1 = qB1;
    }

    #pragma unroll
    for (int nt = 0; nt < 8; nt++) {
        int c = nt * 8 + 2 * t;
        float add0 = __ldg(skip_b + c), add1 = __ldg(skip_b + c + 1);
        if (vA) { float2 v; v.x = D[nt][0] + add0; v.y = D[nt][1] + add1; *(float2*)(g_xs + (size_t)rA * 64 + c) = v; }
        if (vB) { float2 v; v.x = D[nt][2] + add0; v.y = D[nt][3] + add1; *(float2*)(g_xs + (size_t)rB * 64 + c) = v; }
    }
}

// ---------------- K2: per-dst softmax-aggregate, no-max, 2 edges/warp, float4 ----------------
__global__ __launch_bounds__(256) void k_edge(
    const float* __restrict__ att, const float* __restrict__ conv_bias, int N, int E)
{
    int gw = (blockIdx.x * blockDim.x + threadIdx.x) >> 5;
    if (gw >= N) return;
    int lane = threadIdx.x & 31;
    int half = lane >> 4;
    int l = lane & 15;
    int d = gw;
    unsigned hmask = half ? 0xFFFF0000u : 0x0000FFFFu;

    const float4* xl4 = (const float4*)g_xl;
    float4 xr = __ldg((const float4*)g_xr + (size_t)d * 16 + l);
    float4 at = __ldg((const float4*)att + l);

    float den = 0.f, s0 = 0.f, s1 = 0.f, s2 = 0.f, s3 = 0.f;

    int e0  = g_off[d];
    int end = (d + 1 < N) ? g_off[d + 1] : E;
    int nE  = end - e0;
    int cnt = (nE - half + 1) >> 1;
    if (cnt < 0) cnt = 0;
    int base = e0 + half;

    if (half == 1) {
        float4 v = __ldg(xl4 + (size_t)d * 16 + l);
        float t0 = v.x + xr.x, t1 = v.y + xr.y, t2 = v.z + xr.z, t3 = v.w + xr.w;
        t0 = t0 > 0.f ? t0 : 0.2f * t0;
        t1 = t1 > 0.f ? t1 : 0.2f * t1;
        t2 = t2 > 0.f ? t2 : 0.2f * t2;
        t3 = t3 > 0.f ? t3 : 0.2f * t3;
        float p = fmaf(t0, at.x, fmaf(t1, at.y, fmaf(t2, at.z, t3 * at.w)));
        p += __shfl_xor_sync(hmask, p, 1);
        p += __shfl_xor_sync(hmask, p, 2);
        float ex = __expf(p);
        den += ex;
        s0 = fmaf(v.x, ex, s0);
        s1 = fmaf(v.y, ex, s1);
        s2 = fmaf(v.z, ex, s2);
        s3 = fmaf(v.w, ex, s3);
    } else {
        float p = 0.f;
        p += __shfl_xor_sync(hmask, p, 1);
        p += __shfl_xor_sync(hmask, p, 2);
    }

    #pragma unroll 4
    for (int it = 0; it < cnt; it++) {
        int src = __ldg(&g_csr[base + 2 * it]);
        float4 v = __ldg(xl4 + (size_t)src * 16 + l);
        float t0 = v.x + xr.x, t1 = v.y + xr.y, t2 = v.z + xr.z, t3 = v.w + xr.w;
        t0 = t0 > 0.f ? t0 : 0.2f * t0;
        t1 = t1 > 0.f ? t1 : 0.2f * t1;
        t2 = t2 > 0.f ? t2 : 0.2f * t2;
        t3 = t3 > 0.f ? t3 : 0.2f * t3;
        float p = fmaf(t0, at.x, fmaf(t1, at.y, fmaf(t2, at.z, t3 * at.w)));
        p += __shfl_xor_sync(hmask, p, 1);
        p += __shfl_xor_sync(hmask, p, 2);
        float ex = __expf(p);
        den += ex;
        s0 = fmaf(v.x, ex, s0);
        s1 = fmaf(v.y, ex, s1);
        s2 = fmaf(v.z, ex, s2);
        s3 = fmaf(v.w, ex, s3);
    }

    __syncwarp();
    den += __shfl_xor_sync(0xffffffffu, den, 16);
    s0  += __shfl_xor_sync(0xffffffffu, s0, 16);
    s1  += __shfl_xor_sync(0xffffffffu, s1, 16);
    s2  += __shfl_xor_sync(0xffffffffu, s2, 16);
    s3  += __shfl_xor_sync(0xffffffffu, s3, 16);

    if (half == 0) {
        float inv = 1.f / den;
        float4 cb = __ldg((const float4*)conv_bias + l);
        float4 o;
        o.x = fmaf(s0, inv, cb.x);
        o.y = fmaf(s1, inv, cb.y);
        o.z = fmaf(s2, inv, cb.z);
        o.w = fmaf(s3, inv, cb.w);
        ((float4*)g_out)[(size_t)d * 16 + l] = o;
    }
}

// ---------------- K3a: skip-branch sums ----------------
__global__ __launch_bounds__(256) void k_statsS(const int* __restrict__ batch, int N)
{
    int gid = blockIdx.x * blockDim.x + threadIdx.x;
    int ch = gid & 63;
    int slot = gid >> 6;
    int n0 = slot * 32;
    if (n0 >= N) return;
    int n1 = min(n0 + 32, N);

    int gfirst = batch[n0], glast = batch[n1 - 1];
    if (gfirst == glast) {
        float aS = 0.f, qS = 0.f;
        #pragma unroll 4
        for (int n = n0; n < n1; n++) {
            float vs = g_xs[(size_t)n * 64 + ch];
            aS += vs; qS = fmaf(vs, vs, qS);
        }
        atomicAdd(&g_sumS[gfirst * 64 + ch], aS);
        atomicAdd(&g_sqS [gfirst * 64 + ch], qS);
        if (ch == 0) atomicAdd(&g_cnt[gfirst], (float)(n1 - n0));
        return;
    }

    float aS = 0.f, qS = 0.f, ac = 0.f;
    int curg = gfirst;
    for (int n = n0; n < n1; n++) {
        int g = batch[n];
        if (g != curg) {
            atomicAdd(&g_sumS[curg * 64 + ch], aS);
            atomicAdd(&g_sqS [curg * 64 + ch], qS);
            if (ch == 0) atomicAdd(&g_cnt[curg], ac);
            aS = qS = ac = 0.f; curg = g;
        }
        float vs = g_xs[(size_t)n * 64 + ch];
        aS += vs; qS = fmaf(vs, vs, qS);
        ac += 1.f;
    }
    atomicAdd(&g_sumS[curg * 64 + ch], aS);
    atomicAdd(&g_sqS [curg * 64 + ch], qS);
    if (ch == 0) atomicAdd(&g_cnt[curg], ac);
}

// ---------------- K3b: main-branch sums ----------------
__global__ __launch_bounds__(256) void k_statsM(const int* __restrict__ batch, int N)
{
    int gid = blockIdx.x * blockDim.x + threadIdx.x;
    int ch = gid & 63;
    int slot = gid >> 6;
    int n0 = slot * 32;
    if (n0 >= N) return;
    int n1 = min(n0 + 32, N);

    int gfirst = batch[n0], glast = batch[n1 - 1];
    if (gfirst == glast) {
        float aM = 0.f, qM = 0.f;
        #pragma unroll 4
        for (int n = n0; n < n1; n++) {
            float vm = g_out[(size_t)n * 64 + ch];
            aM += vm; qM = fmaf(vm, vm, qM);
        }
        atomicAdd(&g_sumM[gfirst * 64 + ch], aM);
        atomicAdd(&g_sqM [gfirst * 64 + ch], qM);
        return;
    }

    float aM = 0.f, qM = 0.f;
    int curg = gfirst;
    for (int n = n0; n < n1; n++) {
        int g = batch[n];
        if (g != curg) {
            atomicAdd(&g_sumM[curg * 64 + ch], aM);
            atomicAdd(&g_sqM [curg * 64 + ch], qM);
            aM = qM = 0.f; curg = g;
        }
        float vm = g_out[(size_t)n * 64 + ch];
        aM += vm; qM = fmaf(vm, vm, qM);
    }
    atomicAdd(&g_sumM[curg * 64 + ch], aM);
    atomicAdd(&g_sqM [curg * 64 + ch], qM);
}

// ---------------- K3c: precompute affine coeffs ----------------
__global__ void k_prec(
    const float* __restrict__ bn_w, const float* __restrict__ bn_b, const float* __restrict__ bn_ms,
    const float* __restrict__ sn_w, const float* __restrict__ sn_b, const float* __restrict__ sn_ms)
{
    int i = blockIdx.x * blockDim.x + threadIdx.x;
    if (i >= G_NUM * 64) return;
    int g = i >> 6, ch = i & 63;
    float cntv = fmaxf(g_cnt[g], 1.f);
    float rinv = 1.f / cntv;
    float msM = bn_ms[ch], msS = sn_ms[ch];

    float meanM = g_sumM[i] * rinv;
    float eqM   = g_sqM [i] * rinv;
    float varM  = fmaxf(eqM - meanM * meanM * msM * (2.f - msM), 0.f);
    float meanS = g_sumS[i] * rinv;
    float eqS   = g_sqS [i] * rinv;
    float varS  = fmaxf(eqS - meanS * meanS * msS * (2.f - msS), 0.f);

    float cM = bn_w[ch] * rsqrtf(varM + 1e-5f);
    float cS = sn_w[ch] * rsqrtf(varS + 1e-5f);
    float C  = bn_b[ch] + sn_b[ch] - cM * meanM * msM - cS * meanS * msS;
    g_sumM[i] = cM;
    g_sumS[i] = cS;
    g_sqM [i] = C;
}

// ---------------- K4: y = cM*vm + cS*vs + C, then ELU (float4) ----------------
__global__ __launch_bounds__(256) void k_final(
    const int* __restrict__ batch, float* __restrict__ out, int N)
{
    int i = blockIdx.x * blockDim.x + threadIdx.x;
    if (i >= N * 16) return;
    int n = i >> 4, q = i & 15;
    int g = batch[n];

    float4 cM = ((const float4*)g_sumM)[g * 16 + q];
    float4 cS = ((const float4*)g_sumS)[g * 16 + q];
    float4 C  = ((const float4*)g_sqM )[g * 16 + q];
    float4 vm = ((const float4*)g_out)[i];
    float4 vs = ((const float4*)g_xs)[i];

    float4 res;
    float y;
    y = fmaf(cM.x, vm.x, fmaf(cS.x, vs.x, C.x)); res.x = (y > 0.f) ? y : (__expf(y) - 1.f);
    y = fmaf(cM.y, vm.y, fmaf(cS.y, vs.y, C.y)); res.y = (y > 0.f) ? y : (__expf(y) - 1.f);
    y = fmaf(cM.z, vm.z, fmaf(cS.z, vs.z, C.z)); res.z = (y > 0.f) ? y : (__expf(y) - 1.f);
    y = fmaf(cM.w, vm.w, fmaf(cS.w, vs.w, C.w)); res.w = (y > 0.f) ? y : (__expf(y) - 1.f);
    ((float4*)out)[i] = res;
}

// ---------------- launch ----------------
extern "C" void kernel_launch(void* const* d_in, const int* in_sizes, int n_in,
                              void* d_out, int out_size)
{
    const float* x         = (const float*)d_in[0];
    const int*   ei        = (const int*)d_in[1];
    const int*   batch     = (const int*)d_in[2];
    const float* Wl        = (const float*)d_in[3];
    const float* Wr        = (const float*)d_in[4];
    const float* att       = (const float*)d_in[5];
    const float* conv_bias = (const float*)d_in[6];
    const float* skip_W    = (const float*)d_in[7];
    const float* skip_b    = (const float*)d_in[8];
    const float* bn_w      = (const float*)d_in[9];
    const float* bn_b      = (const float*)d_in[10];
    const float* bn_ms     = (const float*)d_in[11];
    const float* sn_w      = (const float*)d_in[12];
    const float* sn_b      = (const float*)d_in[13];
    const float* sn_ms     = (const float*)d_in[14];
    float*       out       = (float*)d_out;

    int N  = in_sizes[0] / 128;
    int E  = in_sizes[1] / 2;
    int nb = (N + 1023) / 1024;

    static cudaStream_t s1 = nullptr, s2 = nullptr;
    static cudaEvent_t evFork = nullptr, evJoin = nullptr, evLR = nullptr, evS2 = nullptr;
    if (s1 == nullptr) {
        cudaStreamCreateWithFlags(&s1, cudaStreamNonBlocking);
        cudaStreamCreateWithFlags(&s2, cudaStreamNonBlocking);
        cudaEventCreateWithFlags(&evFork, cudaEventDisableTiming);
        cudaEventCreateWithFlags(&evJoin, cudaEventDisableTiming);
        cudaEventCreateWithFlags(&evLR, cudaEventDisableTiming);
        cudaEventCreateWithFlags(&evS2, cudaEventDisableTiming);
        cudaFuncSetAttribute(k_gemm_lr, cudaFuncAttributeMaxDynamicSharedMemorySize, SM_LR);
        cudaFuncSetAttribute(k_gemm_s,  cudaFuncAttributeMaxDynamicSharedMemorySize, SM_S);
    }

    // fork
    cudaEventRecord(evFork, 0);
    cudaStreamWaitEvent(s1, evFork, 0);
    cudaStreamWaitEvent(s2, evFork, 0);

    // #1: wprep (main)
    k_wprep<<<(8 * 24 * 32 + 255) / 256, 256>>>(Wl, Wr, skip_W);
    // #2-#3: CSR chain start (s1)
    k_init <<<(N + 255) / 256, 256, 0, s1>>>(N);
    k_hist <<<(E + 255) / 256, 256, 0, s1>>>(ei, E);
    // #4: gemm_lr (main) <- profiled slot
    k_gemm_lr<<<(N + 127) / 128, 512, SM_LR>>>(x, N);
    cudaEventRecord(evLR, 0);
    // rest of CSR chain (s1)
    k_scan1<<<nb, 1024, 0, s1>>>(N);
    k_scan2<<<1, 1024, 0, s1>>>(nb);
    k_scan3<<<(N + 255) / 256, 256, 0, s1>>>(N);
    k_fill <<<(E + 255) / 256, 256, 0, s1>>>(ei, E);
    cudaEventRecord(evJoin, s1);

    // s2: xs GEMM + statsS, concurrent with edge (needs wprep done -> main order gives
    // evLR after gemm_lr which is after wprep; statsS needs k_init (zeroed sums) -> evJoin)
    cudaStreamWaitEvent(s2, evLR, 0);
    k_gemm_s<<<(N + 127) / 128, 256, SM_S, s2>>>(x, skip_b, N);
    cudaStreamWaitEvent(s2, evJoin, 0);
    {
        int slots = (N + 31) / 32;
        long long threads = (long long)slots * 64;
        k_statsS<<<(unsigned)((threads + 255) / 256), 256, 0, s2>>>(batch, N);
    }
    cudaEventRecord(evS2, s2);

    // main: edge needs gemm_lr (same stream) + CSR
    cudaStreamWaitEvent(0, evJoin, 0);
    {
        long long threads = (long long)N * 32;
        k_edge<<<(unsigned)((threads + 255) / 256), 256>>>(att, conv_bias, N, E);
    }
    {
        int slots = (N + 31) / 32;
        long long threads = (long long)slots * 64;
        k_statsM<<<(unsigned)((threads + 255) / 256), 256>>>(batch, N);
    }
    cudaStreamWaitEvent(0, evS2, 0);
    k_prec<<<(G_NUM * 64 + 255) / 256, 256>>>(bn_w, bn_b, bn_ms, sn_w, sn_b, sn_ms);
    {
        long long total = (long long)N * 16;
        k_final<<<(unsigned)((total + 255) / 256), 256>>>(batch, out, N);
    }
}